// round 13
// baseline (speedup 1.0000x reference)
#include <cuda_runtime.h>
#include <cuda_bf16.h>
#include <cstdint>

#define TT 1024
#define BX 128
#define NIJ (BX * BX)
#define NCHUNK 146       // block 0: steps [0,8); block b>0: [7b+1, 7b+8)

// scratch: local prefix products, layout [t][i*128+j]; 64 MB
__device__ float g_scratch[TT * NIJ];

__device__ __forceinline__ uint32_t smem_u32(const void* p) {
    uint32_t a;
    asm("{ .reg .u64 t; cvta.to.shared.u64 t, %1; cvt.u32.u64 %0, t; }"
        : "=r"(a) : "l"(p));
    return a;
}
__device__ __forceinline__ void ldsm_x4(uint32_t& r0, uint32_t& r1,
                                        uint32_t& r2, uint32_t& r3,
                                        uint32_t addr) {
    asm volatile("ldmatrix.sync.aligned.m8n8.x4.shared.b16 {%0,%1,%2,%3}, [%4];"
                 : "=r"(r0), "=r"(r1), "=r"(r2), "=r"(r3) : "r"(addr));
}
__device__ __forceinline__ void mma16816(float* c, const uint32_t* a,
                                         uint32_t b0, uint32_t b1) {
    asm volatile(
        "mma.sync.aligned.m16n8k16.row.col.f32.bf16.bf16.f32 "
        "{%0,%1,%2,%3}, {%4,%5,%6,%7}, {%8,%9}, {%0,%1,%2,%3};"
        : "+f"(c[0]), "+f"(c[1]), "+f"(c[2]), "+f"(c[3])
        : "r"(a[0]), "r"(a[1]), "r"(a[2]), "r"(a[3]), "r"(b0), "r"(b1));
}
__device__ __forceinline__ uint32_t bcat(__nv_bfloat16 a, __nv_bfloat16 b) {
    __nv_bfloat162 t = __halves2bfloat162(a, b);
    return *reinterpret_cast<uint32_t*>(&t);
}

// Phase 1 (HMMA): block b computes local prefix products over steps
// [7b+1, 7b+8) (block 0: [0,8)). Per step, Z = (1023 dX) dY^T via bf16-split
// K=192 concat A=[Xhi|Xhi|Xlo], B=[Yhi|Ylo|Yhi] (hh + hl + lh in one pass).
// Row s (fp32) is kept in smem raw buffers; each step LDGs only row s+1
// (64 KB/step) and diffs against smem -> every input element is read from
// global exactly once per chunk.
__global__ __launch_bounds__(512, 1)
void nsk_phase1(const float4* __restrict__ X4, const float4* __restrict__ Y4) {
    extern __shared__ char smc[];
    __nv_bfloat16* sA = (__nv_bfloat16*)smc;            // [128][200] bf16
    __nv_bfloat16* sB = (__nv_bfloat16*)(smc + 51200);  // [128][200] bf16
    float* rawX = (float*)(smc + 102400);               // [128][64] f32
    float* rawY = (float*)(smc + 135168);               // [128][64] f32
    const uint32_t aA = smem_u32(sA);
    const uint32_t aB = smem_u32(sB);

    const int tid = threadIdx.x;
    const int wid = tid >> 5;
    const int lane = tid & 31;

    // conversion role
    const int crow = tid >> 2;           // 0..127
    const int cq = tid & 3;              // d-quad of 16
    const int gbase = crow * 16384 + cq * 4;
    // mma tile role
    const int m0 = (wid >> 2) * 32;
    const int n0 = (wid & 3) * 32;
    const int grp = lane >> 3, lrow = lane & 7;
    const uint32_t offA = (uint32_t)((lrow + 8 * (grp & 1)) * 400 + 16 * (grp >> 1));
    const uint32_t offB = (uint32_t)((lrow + 8 * (grp >> 1)) * 400 + 16 * (grp & 1));
    const int g = lane >> 2, tg = lane & 3;

    const int b = blockIdx.x;
    const int s_start = (b == 0) ? 0 : 7 * b + 1;
    const int s_end = 7 * b + 8;         // max 1023 at b=145

    float4* rX = (float4*)(rawX + crow * 64 + cq * 16);
    float4* rY = (float4*)(rawY + crow * 64 + cq * 16);

    float k[2][4][4];
#pragma unroll
    for (int a = 0; a < 2; a++)
#pragma unroll
        for (int c = 0; c < 4; c++)
#pragma unroll
            for (int e = 0; e < 4; e++) k[a][c][e] = 1.0f;

    // prologue: raw buffers <- row s_start
    {
        const int gb = gbase + s_start * 16;
#pragma unroll
        for (int c = 0; c < 4; ++c) { rX[c] = X4[gb + c]; rY[c] = Y4[gb + c]; }
    }
    __syncthreads();

    for (int s = s_start; s < s_end; ++s) {
        // ---- LDG row s+1 (the only global traffic this step)
        float4 gx[4], gy[4];
        {
            const int gb = gbase + (s + 1) * 16;
#pragma unroll
            for (int c = 0; c < 4; ++c) { gx[c] = X4[gb + c]; gy[c] = Y4[gb + c]; }
        }
        // ---- diffs vs smem-resident row s
        float fx[16], fy[16];
#pragma unroll
        for (int c = 0; c < 4; ++c) {
            float4 rv = rX[c];
            fx[4 * c + 0] = (gx[c].x - rv.x) * 1023.0f;
            fx[4 * c + 1] = (gx[c].y - rv.y) * 1023.0f;
            fx[4 * c + 2] = (gx[c].z - rv.z) * 1023.0f;
            fx[4 * c + 3] = (gx[c].w - rv.w) * 1023.0f;
            float4 sv = rY[c];
            fy[4 * c + 0] = gy[c].x - sv.x;
            fy[4 * c + 1] = gy[c].y - sv.y;
            fy[4 * c + 2] = gy[c].z - sv.z;
            fy[4 * c + 3] = gy[c].w - sv.w;
        }

        __syncthreads();   // B1: all raw reads + all tile reads (MMA s-1) done

        // ---- raw <- row s+1 (for the next step)
#pragma unroll
        for (int c = 0; c < 4; ++c) { rX[c] = gx[c]; rY[c] = gy[c]; }

        // ---- convert diffs -> bf16 hi/lo, STS tiles (K=192 layout)
        {
            uint32_t xh[8], xl[8], yh[8], yl[8];
#pragma unroll
            for (int m = 0; m < 8; ++m) {
                float u = fx[2 * m], v = fx[2 * m + 1];
                __nv_bfloat16 uh = __float2bfloat16_rn(u);
                __nv_bfloat16 vh = __float2bfloat16_rn(v);
                xh[m] = bcat(uh, vh);
                xl[m] = bcat(__float2bfloat16_rn(u - __bfloat162float(uh)),
                             __float2bfloat16_rn(v - __bfloat162float(vh)));
                float p = fy[2 * m], q = fy[2 * m + 1];
                __nv_bfloat16 ph = __float2bfloat16_rn(p);
                __nv_bfloat16 qh = __float2bfloat16_rn(q);
                yh[m] = bcat(ph, qh);
                yl[m] = bcat(__float2bfloat16_rn(p - __bfloat162float(ph)),
                             __float2bfloat16_rn(q - __bfloat162float(qh)));
            }
            char* pa = (char*)sA + crow * 400 + cq * 32;
            ((uint4*)pa)[0] = ((uint4*)xh)[0];
            ((uint4*)(pa + 16))[0] = ((uint4*)xh)[1];
            ((uint4*)(pa + 128))[0] = ((uint4*)xh)[0];      // Xhi copy 2
            ((uint4*)(pa + 144))[0] = ((uint4*)xh)[1];
            ((uint4*)(pa + 256))[0] = ((uint4*)xl)[0];      // Xlo
            ((uint4*)(pa + 272))[0] = ((uint4*)xl)[1];
            char* pb = (char*)sB + crow * 400 + cq * 32;
            ((uint4*)pb)[0] = ((uint4*)yh)[0];              // Yhi
            ((uint4*)(pb + 16))[0] = ((uint4*)yh)[1];
            ((uint4*)(pb + 128))[0] = ((uint4*)yl)[0];      // Ylo
            ((uint4*)(pb + 144))[0] = ((uint4*)yl)[1];
            ((uint4*)(pb + 256))[0] = ((uint4*)yh)[0];      // Yhi copy 2
            ((uint4*)(pb + 272))[0] = ((uint4*)yh)[1];
        }
        __syncthreads();   // B2: tiles + raw visible

        // ---- 12 k-chunks of 16 over the K=192 concat
        float cacc[2][4][4];
#pragma unroll
        for (int mf = 0; mf < 2; mf++)
#pragma unroll
            for (int nf = 0; nf < 4; nf++)
#pragma unroll
                for (int e = 0; e < 4; e++) cacc[mf][nf][e] = 0.0f;

#pragma unroll
        for (int kc = 0; kc < 12; ++kc) {
            const uint32_t kb = kc * 32;
            uint32_t af0[4], af1[4], b0r[4], b1r[4];
            ldsm_x4(af0[0], af0[1], af0[2], af0[3], aA + m0 * 400 + kb + offA);
            ldsm_x4(af1[0], af1[1], af1[2], af1[3], aA + (m0 + 16) * 400 + kb + offA);
            ldsm_x4(b0r[0], b0r[1], b0r[2], b0r[3], aB + n0 * 400 + kb + offB);
            ldsm_x4(b1r[0], b1r[1], b1r[2], b1r[3], aB + (n0 + 16) * 400 + kb + offB);
            mma16816(cacc[0][0], af0, b0r[0], b0r[1]);
            mma16816(cacc[0][1], af0, b0r[2], b0r[3]);
            mma16816(cacc[0][2], af0, b1r[0], b1r[1]);
            mma16816(cacc[0][3], af0, b1r[2], b1r[3]);
            mma16816(cacc[1][0], af1, b0r[0], b0r[1]);
            mma16816(cacc[1][1], af1, b0r[2], b0r[3]);
            mma16816(cacc[1][2], af1, b1r[0], b1r[1]);
            mma16816(cacc[1][3], af1, b1r[2], b1r[3]);
        }

        // ---- epilogue: k *= (1+z); float2 stores, scratch[t][i*128+j]
        float* base = g_scratch + (size_t)(s + 1) * NIJ;
#pragma unroll
        for (int mf = 0; mf < 2; mf++) {
#pragma unroll
            for (int nf = 0; nf < 4; nf++) {
                const int i0 = m0 + mf * 16 + g;
                const int j = n0 + nf * 8 + tg * 2;
                float* c4 = cacc[mf][nf];
                float* kk = k[mf][nf];
                float k0 = fmaf(c4[0], kk[0], kk[0]);
                float k1 = fmaf(c4[1], kk[1], kk[1]);
                float k2 = fmaf(c4[2], kk[2], kk[2]);
                float k3 = fmaf(c4[3], kk[3], kk[3]);
                kk[0] = k0; kk[1] = k1; kk[2] = k2; kk[3] = k3;
                *(float2*)(base + i0 * BX + j) = make_float2(k0, k1);
                *(float2*)(base + (i0 + 8) * BX + j) = make_float2(k2, k3);
            }
        }
    }
}

// Phase 2 (fused): grid (512 strips, 2 t-halves). Each block scans the 146
// chunk totals for its 32-ij strip, then processes 8 of the 16 t-tiles.
// Chunk owner of t>=1 is c = (t-2)/7 (t=1 -> 0), precomputed in a smem table.
__global__ __launch_bounds__(256)
void nsk_phase2f(float* __restrict__ out) {
    extern __shared__ float sm[];
    float* cend = sm;                    // [146][32] -> exclusive scales
    float* qp = sm + NCHUNK * 32;        // [8][32]
    float* tile = qp + 8 * 32;           // [64][33]
    unsigned char* ct = (unsigned char*)(tile + 64 * 33);  // [1024]

    const int tid = threadIdx.x;
    const int lane = tid & 31;
    const int q = tid >> 5;              // 0..7
    const int lane64 = tid & 63;
    const int colg = tid >> 6;           // 0..3
    const int ij0 = blockIdx.x * 32;
    const int half = blockIdx.y;

    // build owner table + load chunk-end values
    for (int t = tid; t < TT; t += 256)
        ct[t] = (t < 2) ? 0 : (unsigned char)((t - 2) / 7);
#pragma unroll
    for (int cc = 0; cc < 19; cc++) {
        const int c = q + 8 * cc;
        if (c < NCHUNK) {
            const int e = 7 * c + 8;
            cend[c * 32 + lane] = g_scratch[(size_t)e * NIJ + ij0 + lane];
        }
    }
    __syncthreads();
    {
        float p = 1.0f;
#pragma unroll 1
        for (int cc = 0; cc < 19; cc++) {
            const int c = 19 * q + cc;
            if (c < NCHUNK) {
                const float v = cend[c * 32 + lane];
                cend[c * 32 + lane] = p;
                p *= v;
            }
        }
        qp[q * 32 + lane] = p;
    }
    __syncthreads();
    if (q > 0) {
        float off = qp[lane];
#pragma unroll
        for (int w = 1; w < 7; w++)
            if (q > w) off *= qp[w * 32 + lane];
#pragma unroll 1
        for (int cc = 0; cc < 19; cc++) {
            const int c = 19 * q + cc;
            if (c < NCHUNK) cend[c * 32 + lane] *= off;
        }
    }
    __syncthreads();

    // 8 tiles of 64 t-rows x 32 ij (this block's t-half)
#pragma unroll 1
    for (int ti = 8 * half; ti < 8 * half + 8; ti++) {
        const int t0 = ti * 64;
#pragma unroll
        for (int rr = 0; rr < 8; rr++) {
            const int r = q + 8 * rr;
            const int t = t0 + r;
            if (t == 0) {
                tile[r * 33 + lane] = 1.0f;
            } else {
                const int c = ct[t];       // broadcast LDS.U8
                const float v = g_scratch[(size_t)t * NIJ + ij0 + lane];
                tile[r * 33 + lane] = v * cend[c * 32 + lane];
            }
        }
        __syncthreads();
#pragma unroll
        for (int cc = 0; cc < 8; cc++) {
            const int col = colg + 4 * cc;
            out[(size_t)(ij0 + col) * TT + t0 + lane64] = tile[lane64 * 33 + col];
        }
        __syncthreads();
    }
}

extern "C" void kernel_launch(void* const* d_in, const int* in_sizes, int n_in,
                              void* d_out, int out_size) {
    const float4* X4 = (const float4*)d_in[0];
    const float4* Y4 = (const float4*)d_in[1];
    float* out = (float*)d_out;

    const int smem1 = 102400 + 2 * 32768;                                     // 167936 B
    const int smem2 = (NCHUNK * 32 + 8 * 32 + 64 * 33) * (int)sizeof(float)
                      + 1024;                                                 // 29184 B
    cudaFuncSetAttribute(nsk_phase1, cudaFuncAttributeMaxDynamicSharedMemorySize, smem1);
    cudaFuncSetAttribute(nsk_phase2f, cudaFuncAttributeMaxDynamicSharedMemorySize, smem2);

    nsk_phase1<<<NCHUNK, 512, smem1>>>(X4, Y4);
    nsk_phase2f<<<dim3(NIJ / 32, 2), 256, smem2>>>(out);
}

// round 14
// speedup vs baseline: 1.1531x; 1.1531x over previous
#include <cuda_runtime.h>
#include <cuda_bf16.h>
#include <cstdint>

#define TT 1024
#define BX 128
#define NIJ (BX * BX)
#define NCHUNK 146       // block 0: steps [0,8); block b>0: [7b+1, 7b+8)

// smem layout (bytes)
#define T_A    0         // A tiles [128][272B]: cols 0-63 Xhi, 64-127 Xlo
#define T_B    34816     // B tiles [128][272B]: Yhi | Ylo
#define RAW0X  69632     // raw fp32 rows, stride 272B: [128][68f]
#define RAW0Y  104448
#define RAW1X  139264
#define RAW1Y  174080
#define SM1_TOTAL 208896

// scratch: local prefix products, layout [t][i*128+j]; 64 MB
__device__ float g_scratch[TT * NIJ];

__device__ __forceinline__ uint32_t smem_u32(const void* p) {
    uint32_t a;
    asm("{ .reg .u64 t; cvta.to.shared.u64 t, %1; cvt.u32.u64 %0, t; }"
        : "=r"(a) : "l"(p));
    return a;
}
__device__ __forceinline__ void cpa16(uint32_t dst, const void* src) {
    asm volatile("cp.async.cg.shared.global [%0], [%1], 16;"
                 :: "r"(dst), "l"(src));
}
__device__ __forceinline__ void ldsm_x4(uint32_t& r0, uint32_t& r1,
                                        uint32_t& r2, uint32_t& r3,
                                        uint32_t addr) {
    asm volatile("ldmatrix.sync.aligned.m8n8.x4.shared.b16 {%0,%1,%2,%3}, [%4];"
                 : "=r"(r0), "=r"(r1), "=r"(r2), "=r"(r3) : "r"(addr));
}
__device__ __forceinline__ void mma16816(float* c, const uint32_t* a,
                                         uint32_t b0, uint32_t b1) {
    asm volatile(
        "mma.sync.aligned.m16n8k16.row.col.f32.bf16.bf16.f32 "
        "{%0,%1,%2,%3}, {%4,%5,%6,%7}, {%8,%9}, {%0,%1,%2,%3};"
        : "+f"(c[0]), "+f"(c[1]), "+f"(c[2]), "+f"(c[3])
        : "r"(a[0]), "r"(a[1]), "r"(a[2]), "r"(a[3]), "r"(b0), "r"(b1));
}
__device__ __forceinline__ uint32_t bcat(__nv_bfloat16 a, __nv_bfloat16 b) {
    __nv_bfloat162 t = __halves2bfloat162(a, b);
    return *reinterpret_cast<uint32_t*>(&t);
}

// Phase 1 (HMMA + cp.async pipeline): block b handles steps [7b+1, 7b+8)
// (block 0: [0,8)). Z = (1023 dX) dY^T via bf16 split; hh + hl + lh realized
// by k-chunk pairing over A=[Xhi|Xlo], B=[Yhi|Ylo]. Raw fp32 rows are
// double-buffered in smem via per-thread cp.async (row s+2 prefetched during
// step s's MMA), so LDG latency is off the critical path.
__global__ __launch_bounds__(512, 1)
void nsk_phase1(const float4* __restrict__ X4, const float4* __restrict__ Y4) {
    extern __shared__ char smc[];
    const uint32_t sb = smem_u32(smc);
    const uint32_t aA = sb + T_A;
    const uint32_t aB = sb + T_B;

    const int tid = threadIdx.x;
    const int wid = tid >> 5;
    const int lane = tid & 31;

    // loader/convert role: (row, 64B quarter)
    const int crow = tid >> 2;           // 0..127
    const int cq = tid & 3;              // 0..3
    const int roff = crow * 272 + cq * 64;   // byte offset inside a raw buffer
    const float4* gX = X4 + crow * 16384 + cq * 4;
    const float4* gY = Y4 + crow * 16384 + cq * 4;
    // mma tile role
    const int m0 = (wid >> 2) * 32;
    const int n0 = (wid & 3) * 32;
    const int grp = lane >> 3, lrow = lane & 7;
    const uint32_t offA = (uint32_t)((lrow + 8 * (grp & 1)) * 272 + 16 * (grp >> 1));
    const uint32_t offB = (uint32_t)((lrow + 8 * (grp >> 1)) * 272 + 16 * (grp & 1));
    const int g = lane >> 2, tg = lane & 3;

    const int b = blockIdx.x;
    const int s_start = (b == 0) ? 0 : 7 * b + 1;
    const int s_end = 7 * b + 8;         // max 1023 at b=145

    const uint32_t rawX[2] = { sb + RAW0X + roff, sb + RAW1X + roff };
    const uint32_t rawY[2] = { sb + RAW0Y + roff, sb + RAW1Y + roff };

    float k[2][4][4];
#pragma unroll
    for (int a = 0; a < 2; a++)
#pragma unroll
        for (int c = 0; c < 4; c++)
#pragma unroll
            for (int e = 0; e < 4; e++) k[a][c][e] = 1.0f;

    // prologue: rows s_start -> buf0, s_start+1 -> buf1
#pragma unroll
    for (int c = 0; c < 4; ++c) {
        cpa16(rawX[0] + c * 16, gX + s_start * 16 + c);
        cpa16(rawY[0] + c * 16, gY + s_start * 16 + c);
        cpa16(rawX[1] + c * 16, gX + (s_start + 1) * 16 + c);
        cpa16(rawY[1] + c * 16, gY + (s_start + 1) * 16 + c);
    }
    asm volatile("cp.async.commit_group;" ::: "memory");

    int p = 0;
    for (int s = s_start; s < s_end; ++s) {
        // wait for raw rows s (buf p) and s+1 (buf p^1)
        asm volatile("cp.async.wait_group 0;" ::: "memory");

        // ---- diffs from smem raw (same-thread region; no barrier needed)
        float fx[16], fy[16];
#pragma unroll
        for (int c = 0; c < 4; ++c) {
            float4 c0 = *(const float4*)(smc + (rawX[p] - sb) + c * 16);
            float4 c1 = *(const float4*)(smc + (rawX[p ^ 1] - sb) + c * 16);
            fx[4 * c + 0] = (c1.x - c0.x) * 1023.0f;
            fx[4 * c + 1] = (c1.y - c0.y) * 1023.0f;
            fx[4 * c + 2] = (c1.z - c0.z) * 1023.0f;
            fx[4 * c + 3] = (c1.w - c0.w) * 1023.0f;
            float4 d0 = *(const float4*)(smc + (rawY[p] - sb) + c * 16);
            float4 d1 = *(const float4*)(smc + (rawY[p ^ 1] - sb) + c * 16);
            fy[4 * c + 0] = d1.x - d0.x;
            fy[4 * c + 1] = d1.y - d0.y;
            fy[4 * c + 2] = d1.z - d0.z;
            fy[4 * c + 3] = d1.w - d0.w;
        }
        // ---- split to bf16 hi/lo (registers)
        uint32_t xh[8], xl[8], yh[8], yl[8];
#pragma unroll
        for (int m = 0; m < 8; ++m) {
            float u = fx[2 * m], v = fx[2 * m + 1];
            __nv_bfloat16 uh = __float2bfloat16_rn(u);
            __nv_bfloat16 vh = __float2bfloat16_rn(v);
            xh[m] = bcat(uh, vh);
            xl[m] = bcat(__float2bfloat16_rn(u - __bfloat162float(uh)),
                         __float2bfloat16_rn(v - __bfloat162float(vh)));
            float pp = fy[2 * m], q = fy[2 * m + 1];
            __nv_bfloat16 ph = __float2bfloat16_rn(pp);
            __nv_bfloat16 qh = __float2bfloat16_rn(q);
            yh[m] = bcat(ph, qh);
            yl[m] = bcat(__float2bfloat16_rn(pp - __bfloat162float(ph)),
                         __float2bfloat16_rn(q - __bfloat162float(qh)));
        }

        __syncthreads();   // B1: all ldsm reads of tiles (step s-1) done

        // ---- STS tiles: A=[Xhi|Xlo], B=[Yhi|Ylo]; 32B per half-row-quarter
        {
            char* pa = smc + T_A + crow * 272 + cq * 32;
            ((uint4*)pa)[0] = ((uint4*)xh)[0];
            ((uint4*)(pa + 16))[0] = ((uint4*)xh)[1];
            ((uint4*)(pa + 128))[0] = ((uint4*)xl)[0];
            ((uint4*)(pa + 144))[0] = ((uint4*)xl)[1];
            char* pb = smc + T_B + crow * 272 + cq * 32;
            ((uint4*)pb)[0] = ((uint4*)yh)[0];
            ((uint4*)(pb + 16))[0] = ((uint4*)yh)[1];
            ((uint4*)(pb + 128))[0] = ((uint4*)yl)[0];
            ((uint4*)(pb + 144))[0] = ((uint4*)yl)[1];
        }

        // ---- prefetch row s+2 into buf p (own region; overlaps MMA)
        {
            const int nr = (s + 2 <= s_end) ? (s + 2) : s_end;
#pragma unroll
            for (int c = 0; c < 4; ++c) {
                cpa16(rawX[p] + c * 16, gX + nr * 16 + c);
                cpa16(rawY[p] + c * 16, gY + nr * 16 + c);
            }
            asm volatile("cp.async.commit_group;" ::: "memory");
        }

        __syncthreads();   // B2: tiles visible to all warps

        // ---- MMA: per kc, load 8 frags, issue hh/hl/lh (24 mma)
        float cacc[2][4][4];
#pragma unroll
        for (int mf = 0; mf < 2; mf++)
#pragma unroll
            for (int nf = 0; nf < 4; nf++)
#pragma unroll
                for (int e = 0; e < 4; e++) cacc[mf][nf][e] = 0.0f;

#pragma unroll
        for (int kc = 0; kc < 4; ++kc) {
            const uint32_t kh = kc * 32;        // hi chunk cols
            const uint32_t kl = 128 + kc * 32;  // lo chunk cols
            uint32_t ah0[4], ah1[4], al0[4], al1[4];
            uint32_t bh0[4], bh1[4], bl0[4], bl1[4];
            ldsm_x4(ah0[0], ah0[1], ah0[2], ah0[3], aA + m0 * 272 + kh + offA);
            ldsm_x4(ah1[0], ah1[1], ah1[2], ah1[3], aA + (m0 + 16) * 272 + kh + offA);
            ldsm_x4(al0[0], al0[1], al0[2], al0[3], aA + m0 * 272 + kl + offA);
            ldsm_x4(al1[0], al1[1], al1[2], al1[3], aA + (m0 + 16) * 272 + kl + offA);
            ldsm_x4(bh0[0], bh0[1], bh0[2], bh0[3], aB + n0 * 272 + kh + offB);
            ldsm_x4(bh1[0], bh1[1], bh1[2], bh1[3], aB + (n0 + 16) * 272 + kh + offB);
            ldsm_x4(bl0[0], bl0[1], bl0[2], bl0[3], aB + n0 * 272 + kl + offB);
            ldsm_x4(bl1[0], bl1[1], bl1[2], bl1[3], aB + (n0 + 16) * 272 + kl + offB);
            // hh
            mma16816(cacc[0][0], ah0, bh0[0], bh0[1]);
            mma16816(cacc[0][1], ah0, bh0[2], bh0[3]);
            mma16816(cacc[0][2], ah0, bh1[0], bh1[1]);
            mma16816(cacc[0][3], ah0, bh1[2], bh1[3]);
            mma16816(cacc[1][0], ah1, bh0[0], bh0[1]);
            mma16816(cacc[1][1], ah1, bh0[2], bh0[3]);
            mma16816(cacc[1][2], ah1, bh1[0], bh1[1]);
            mma16816(cacc[1][3], ah1, bh1[2], bh1[3]);
            // hl: Xhi x Ylo
            mma16816(cacc[0][0], ah0, bl0[0], bl0[1]);
            mma16816(cacc[0][1], ah0, bl0[2], bl0[3]);
            mma16816(cacc[0][2], ah0, bl1[0], bl1[1]);
            mma16816(cacc[0][3], ah0, bl1[2], bl1[3]);
            mma16816(cacc[1][0], ah1, bl0[0], bl0[1]);
            mma16816(cacc[1][1], ah1, bl0[2], bl0[3]);
            mma16816(cacc[1][2], ah1, bl1[0], bl1[1]);
            mma16816(cacc[1][3], ah1, bl1[2], bl1[3]);
            // lh: Xlo x Yhi
            mma16816(cacc[0][0], al0, bh0[0], bh0[1]);
            mma16816(cacc[0][1], al0, bh0[2], bh0[3]);
            mma16816(cacc[0][2], al0, bh1[0], bh1[1]);
            mma16816(cacc[0][3], al0, bh1[2], bh1[3]);
            mma16816(cacc[1][0], al1, bh0[0], bh0[1]);
            mma16816(cacc[1][1], al1, bh0[2], bh0[3]);
            mma16816(cacc[1][2], al1, bh1[0], bh1[1]);
            mma16816(cacc[1][3], al1, bh1[2], bh1[3]);
        }

        // ---- epilogue: k *= (1+z); float2 stores, scratch[t][i*128+j]
        float* base = g_scratch + (size_t)(s + 1) * NIJ;
#pragma unroll
        for (int mf = 0; mf < 2; mf++) {
#pragma unroll
            for (int nf = 0; nf < 4; nf++) {
                const int i0 = m0 + mf * 16 + g;
                const int j = n0 + nf * 8 + tg * 2;
                float* c4 = cacc[mf][nf];
                float* kk = k[mf][nf];
                float k0 = fmaf(c4[0], kk[0], kk[0]);
                float k1 = fmaf(c4[1], kk[1], kk[1]);
                float k2 = fmaf(c4[2], kk[2], kk[2]);
                float k3 = fmaf(c4[3], kk[3], kk[3]);
                kk[0] = k0; kk[1] = k1; kk[2] = k2; kk[3] = k3;
                *(float2*)(base + i0 * BX + j) = make_float2(k0, k1);
                *(float2*)(base + (i0 + 8) * BX + j) = make_float2(k2, k3);
            }
        }
        p ^= 1;
    }
}

// Phase 2 (fused, R12 version): one block per 32-ij strip. Chunk c's last
// written t is e = 7c+8; owner of t>=1 is c = (t-2)/7 (trunc; t=1 -> 0).
__global__ __launch_bounds__(256, 8)
void nsk_phase2f(float* __restrict__ out) {
    extern __shared__ float sm[];
    float* cend = sm;                    // [146][32] -> exclusive scales
    float* qp = sm + NCHUNK * 32;        // [8][32]
    float* tile = qp + 8 * 32;           // [64][33]

    const int tid = threadIdx.x;
    const int lane = tid & 31;
    const int q = tid >> 5;              // 0..7
    const int lane64 = tid & 63;
    const int colg = tid >> 6;           // 0..3
    const int ij0 = blockIdx.x * 32;

#pragma unroll
    for (int cc = 0; cc < 19; cc++) {
        const int c = q + 8 * cc;
        if (c < NCHUNK) {
            const int e = 7 * c + 8;
            cend[c * 32 + lane] = g_scratch[(size_t)e * NIJ + ij0 + lane];
        }
    }
    __syncthreads();
    {
        float p = 1.0f;
#pragma unroll 1
        for (int cc = 0; cc < 19; cc++) {
            const int c = 19 * q + cc;
            if (c < NCHUNK) {
                const float v = cend[c * 32 + lane];
                cend[c * 32 + lane] = p;
                p *= v;
            }
        }
        qp[q * 32 + lane] = p;
    }
    __syncthreads();
    if (q > 0) {
        float off = qp[lane];
#pragma unroll
        for (int w = 1; w < 7; w++)
            if (q > w) off *= qp[w * 32 + lane];
#pragma unroll 1
        for (int cc = 0; cc < 19; cc++) {
            const int c = 19 * q + cc;
            if (c < NCHUNK) cend[c * 32 + lane] *= off;
        }
    }
    __syncthreads();

#pragma unroll 1
    for (int ti = 0; ti < 16; ti++) {
        const int t0 = ti * 64;
#pragma unroll
        for (int rr = 0; rr < 8; rr++) {
            const int r = q + 8 * rr;
            const int t = t0 + r;
            if (t == 0) {
                tile[r * 33 + lane] = 1.0f;
            } else {
                const int c = (t - 2) / 7;   // t=1 -> 0
                const float v = g_scratch[(size_t)t * NIJ + ij0 + lane];
                tile[r * 33 + lane] = v * cend[c * 32 + lane];
            }
        }
        __syncthreads();
#pragma unroll
        for (int cc = 0; cc < 8; cc++) {
            const int col = colg + 4 * cc;
            out[(size_t)(ij0 + col) * TT + t0 + lane64] = tile[lane64 * 33 + col];
        }
        __syncthreads();
    }
}

extern "C" void kernel_launch(void* const* d_in, const int* in_sizes, int n_in,
                              void* d_out, int out_size) {
    const float4* X4 = (const float4*)d_in[0];
    const float4* Y4 = (const float4*)d_in[1];
    float* out = (float*)d_out;

    const int smem2 = (NCHUNK * 32 + 8 * 32 + 64 * 33) * (int)sizeof(float);  // 28160 B
    cudaFuncSetAttribute(nsk_phase1, cudaFuncAttributeMaxDynamicSharedMemorySize,
                         SM1_TOTAL);
    cudaFuncSetAttribute(nsk_phase2f, cudaFuncAttributeMaxDynamicSharedMemorySize,
                         smem2);

    nsk_phase1<<<NCHUNK, 512, SM1_TOTAL>>>(X4, Y4);
    nsk_phase2f<<<NIJ / 32, 256, smem2>>>(out);
}

// round 15
// speedup vs baseline: 1.1700x; 1.0146x over previous
#include <cuda_runtime.h>
#include <cuda_bf16.h>
#include <cstdint>

#define TT 1024
#define BX 128
#define NIJ (BX * BX)
#define NCHUNK 146       // chunk 0: steps [0,8); chunk c>0: [7c+1, 7c+8)

// smem layout (bytes): A tile 64 rows x 272B (Xhi|Xlo), B tile 128 rows x 272B
#define T_A 0
#define T_B 17408
#define SM1_TOTAL 52224

// scratch: local prefix products, layout [t][i*128+j]; 64 MB
__device__ float g_scratch[TT * NIJ];

__device__ __forceinline__ uint32_t smem_u32(const void* p) {
    uint32_t a;
    asm("{ .reg .u64 t; cvta.to.shared.u64 t, %1; cvt.u32.u64 %0, t; }"
        : "=r"(a) : "l"(p));
    return a;
}
__device__ __forceinline__ void ldsm_x4(uint32_t& r0, uint32_t& r1,
                                        uint32_t& r2, uint32_t& r3,
                                        uint32_t addr) {
    asm volatile("ldmatrix.sync.aligned.m8n8.x4.shared.b16 {%0,%1,%2,%3}, [%4];"
                 : "=r"(r0), "=r"(r1), "=r"(r2), "=r"(r3) : "r"(addr));
}
__device__ __forceinline__ void mma16816(float* c, const uint32_t* a,
                                         uint32_t b0, uint32_t b1) {
    asm volatile(
        "mma.sync.aligned.m16n8k16.row.col.f32.bf16.bf16.f32 "
        "{%0,%1,%2,%3}, {%4,%5,%6,%7}, {%8,%9}, {%0,%1,%2,%3};"
        : "+f"(c[0]), "+f"(c[1]), "+f"(c[2]), "+f"(c[3])
        : "r"(a[0]), "r"(a[1]), "r"(a[2]), "r"(a[3]), "r"(b0), "r"(b1));
}
__device__ __forceinline__ uint32_t bcat(__nv_bfloat16 a, __nv_bfloat16 b) {
    __nv_bfloat162 t = __halves2bfloat162(a, b);
    return *reinterpret_cast<uint32_t*>(&t);
}

__global__ void nsk_dummy() {}

// Phase 1 (HMMA, 2 CTAs/SM): 292 blocks; block -> (chunk = b>>1, half = b&1).
// Each CTA owns the 64x128 i-half tile of its chunk and runs the chunk's
// steps serially. Two co-resident CTAs per SM fill each other's load /
// convert / barrier bubbles with MMA work.
// Per step: Z = (1023 dX) dY^T via bf16 split, hh+hl+lh by k-chunk pairing
// over A=[Xhi|Xlo], B=[Yhi|Ylo].
__global__ __launch_bounds__(256, 2)
void nsk_phase1(const float4* __restrict__ X4, const float4* __restrict__ Y4) {
    extern __shared__ char smc[];
    const uint32_t sb = smem_u32(smc);
    const uint32_t aA = sb + T_A;
    const uint32_t aB = sb + T_B;

    const int tid = threadIdx.x;
    const int wid = tid >> 5;
    const int lane = tid & 31;

    const int chunk = blockIdx.x >> 1;
    const int ib = (blockIdx.x & 1) << 6;    // i-half base: 0 or 64

    // conversion roles
    const int xrow = tid >> 2;               // 0..63 (A-tile row)
    const int q = tid & 3;                   // d-quad of 16
    const int gX = (ib + xrow) * 16384 + q * 4;
    const int gY0 = xrow * 16384 + q * 4;            // Y rows 0..63
    const int gY1 = (xrow + 64) * 16384 + q * 4;     // Y rows 64..127
    // mma tile role: 8 warps, 2x4
    const int m0 = (wid >> 2) << 5;          // 0 or 32 (within A tile)
    const int n0 = (wid & 3) << 5;
    const int grp = lane >> 3, lrow = lane & 7;
    const uint32_t offA = (uint32_t)((lrow + 8 * (grp & 1)) * 272 + 16 * (grp >> 1));
    const uint32_t offB = (uint32_t)((lrow + 8 * (grp >> 1)) * 272 + 16 * (grp & 1));
    const int g = lane >> 2, tg = lane & 3;

    const int s_start = (chunk == 0) ? 0 : 7 * chunk + 1;
    const int s_end = 7 * chunk + 8;         // max 1023

    float k[2][4][4];
#pragma unroll
    for (int a = 0; a < 2; a++)
#pragma unroll
        for (int c = 0; c < 4; c++)
#pragma unroll
            for (int e = 0; e < 4; e++) k[a][c][e] = 1.0f;

    for (int s = s_start; s < s_end; ++s) {
        __syncthreads();   // previous step's ldsm reads done

        // ---- X half: 16 values -> hi/lo, STS to A tile
        {
            float fx[16];
#pragma unroll
            for (int c = 0; c < 4; ++c) {
                float4 a0 = X4[gX + s * 16 + c], a1 = X4[gX + (s + 1) * 16 + c];
                fx[4 * c + 0] = (a1.x - a0.x) * 1023.0f;
                fx[4 * c + 1] = (a1.y - a0.y) * 1023.0f;
                fx[4 * c + 2] = (a1.z - a0.z) * 1023.0f;
                fx[4 * c + 3] = (a1.w - a0.w) * 1023.0f;
            }
            uint32_t xh[8], xl[8];
#pragma unroll
            for (int m = 0; m < 8; ++m) {
                float u = fx[2 * m], v = fx[2 * m + 1];
                __nv_bfloat16 uh = __float2bfloat16_rn(u);
                __nv_bfloat16 vh = __float2bfloat16_rn(v);
                xh[m] = bcat(uh, vh);
                xl[m] = bcat(__float2bfloat16_rn(u - __bfloat162float(uh)),
                             __float2bfloat16_rn(v - __bfloat162float(vh)));
            }
            char* pa = smc + T_A + xrow * 272 + q * 32;
            ((uint4*)pa)[0] = ((uint4*)xh)[0];
            ((uint4*)(pa + 16))[0] = ((uint4*)xh)[1];
            ((uint4*)(pa + 128))[0] = ((uint4*)xl)[0];
            ((uint4*)(pa + 144))[0] = ((uint4*)xl)[1];
        }
        // ---- Y halves (two 64-row groups, processed one at a time)
#pragma unroll
        for (int h = 0; h < 2; ++h) {
            const int gb = (h == 0 ? gY0 : gY1);
            float fy[16];
#pragma unroll
            for (int c = 0; c < 4; ++c) {
                float4 b0 = Y4[gb + s * 16 + c], b1 = Y4[gb + (s + 1) * 16 + c];
                fy[4 * c + 0] = b1.x - b0.x;
                fy[4 * c + 1] = b1.y - b0.y;
                fy[4 * c + 2] = b1.z - b0.z;
                fy[4 * c + 3] = b1.w - b0.w;
            }
            uint32_t yh[8], yl[8];
#pragma unroll
            for (int m = 0; m < 8; ++m) {
                float p = fy[2 * m], r = fy[2 * m + 1];
                __nv_bfloat16 ph = __float2bfloat16_rn(p);
                __nv_bfloat16 rh = __float2bfloat16_rn(r);
                yh[m] = bcat(ph, rh);
                yl[m] = bcat(__float2bfloat16_rn(p - __bfloat162float(ph)),
                             __float2bfloat16_rn(r - __bfloat162float(rh)));
            }
            char* pb = smc + T_B + (xrow + 64 * h) * 272 + q * 32;
            ((uint4*)pb)[0] = ((uint4*)yh)[0];
            ((uint4*)(pb + 16))[0] = ((uint4*)yh)[1];
            ((uint4*)(pb + 128))[0] = ((uint4*)yl)[0];
            ((uint4*)(pb + 144))[0] = ((uint4*)yl)[1];
        }
        __syncthreads();   // tiles visible

        // ---- MMA: 4 k-chunks, hh + hl + lh (24 mma each)
        float cacc[2][4][4];
#pragma unroll
        for (int mf = 0; mf < 2; mf++)
#pragma unroll
            for (int nf = 0; nf < 4; nf++)
#pragma unroll
                for (int e = 0; e < 4; e++) cacc[mf][nf][e] = 0.0f;

#pragma unroll
        for (int kc = 0; kc < 4; ++kc) {
            const uint32_t kh = kc * 32;
            const uint32_t kl = 128 + kc * 32;
            uint32_t ah0[4], ah1[4], al0[4], al1[4];
            uint32_t bh0[4], bh1[4], bl0[4], bl1[4];
            ldsm_x4(ah0[0], ah0[1], ah0[2], ah0[3], aA + m0 * 272 + kh + offA);
            ldsm_x4(ah1[0], ah1[1], ah1[2], ah1[3], aA + (m0 + 16) * 272 + kh + offA);
            ldsm_x4(al0[0], al0[1], al0[2], al0[3], aA + m0 * 272 + kl + offA);
            ldsm_x4(al1[0], al1[1], al1[2], al1[3], aA + (m0 + 16) * 272 + kl + offA);
            ldsm_x4(bh0[0], bh0[1], bh0[2], bh0[3], aB + n0 * 272 + kh + offB);
            ldsm_x4(bh1[0], bh1[1], bh1[2], bh1[3], aB + (n0 + 16) * 272 + kh + offB);
            ldsm_x4(bl0[0], bl0[1], bl0[2], bl0[3], aB + n0 * 272 + kl + offB);
            ldsm_x4(bl1[0], bl1[1], bl1[2], bl1[3], aB + (n0 + 16) * 272 + kl + offB);
            mma16816(cacc[0][0], ah0, bh0[0], bh0[1]);
            mma16816(cacc[0][1], ah0, bh0[2], bh0[3]);
            mma16816(cacc[0][2], ah0, bh1[0], bh1[1]);
            mma16816(cacc[0][3], ah0, bh1[2], bh1[3]);
            mma16816(cacc[1][0], ah1, bh0[0], bh0[1]);
            mma16816(cacc[1][1], ah1, bh0[2], bh0[3]);
            mma16816(cacc[1][2], ah1, bh1[0], bh1[1]);
            mma16816(cacc[1][3], ah1, bh1[2], bh1[3]);
            mma16816(cacc[0][0], ah0, bl0[0], bl0[1]);
            mma16816(cacc[0][1], ah0, bl0[2], bl0[3]);
            mma16816(cacc[0][2], ah0, bl1[0], bl1[1]);
            mma16816(cacc[0][3], ah0, bl1[2], bl1[3]);
            mma16816(cacc[1][0], ah1, bl0[0], bl0[1]);
            mma16816(cacc[1][1], ah1, bl0[2], bl0[3]);
            mma16816(cacc[1][2], ah1, bl1[0], bl1[1]);
            mma16816(cacc[1][3], ah1, bl1[2], bl1[3]);
            mma16816(cacc[0][0], al0, bh0[0], bh0[1]);
            mma16816(cacc[0][1], al0, bh0[2], bh0[3]);
            mma16816(cacc[0][2], al0, bh1[0], bh1[1]);
            mma16816(cacc[0][3], al0, bh1[2], bh1[3]);
            mma16816(cacc[1][0], al1, bh0[0], bh0[1]);
            mma16816(cacc[1][1], al1, bh0[2], bh0[3]);
            mma16816(cacc[1][2], al1, bh1[0], bh1[1]);
            mma16816(cacc[1][3], al1, bh1[2], bh1[3]);
        }

        // ---- epilogue: k *= (1+z); float2 stores, scratch[t][i*128+j]
        float* base = g_scratch + (size_t)(s + 1) * NIJ;
#pragma unroll
        for (int mf = 0; mf < 2; mf++) {
#pragma unroll
            for (int nf = 0; nf < 4; nf++) {
                const int i0 = ib + m0 + mf * 16 + g;
                const int j = n0 + nf * 8 + tg * 2;
                float* c4 = cacc[mf][nf];
                float* kk = k[mf][nf];
                float k0 = fmaf(c4[0], kk[0], kk[0]);
                float k1 = fmaf(c4[1], kk[1], kk[1]);
                float k2 = fmaf(c4[2], kk[2], kk[2]);
                float k3 = fmaf(c4[3], kk[3], kk[3]);
                kk[0] = k0; kk[1] = k1; kk[2] = k2; kk[3] = k3;
                *(float2*)(base + i0 * BX + j) = make_float2(k0, k1);
                *(float2*)(base + (i0 + 8) * BX + j) = make_float2(k2, k3);
            }
        }
    }
}

// Phase 2 (fused, verified R12 version): one block per 32-ij strip.
// Chunk c's last written t is e = 7c+8; owner of t>=1 is c = (t-2)/7.
__global__ __launch_bounds__(256, 8)
void nsk_phase2f(float* __restrict__ out) {
    extern __shared__ float sm[];
    float* cend = sm;                    // [146][32] -> exclusive scales
    float* qp = sm + NCHUNK * 32;        // [8][32]
    float* tile = qp + 8 * 32;           // [64][33]

    const int tid = threadIdx.x;
    const int lane = tid & 31;
    const int q = tid >> 5;              // 0..7
    const int lane64 = tid & 63;
    const int colg = tid >> 6;           // 0..3
    const int ij0 = blockIdx.x * 32;

#pragma unroll
    for (int cc = 0; cc < 19; cc++) {
        const int c = q + 8 * cc;
        if (c < NCHUNK) {
            const int e = 7 * c + 8;
            cend[c * 32 + lane] = g_scratch[(size_t)e * NIJ + ij0 + lane];
        }
    }
    __syncthreads();
    {
        float p = 1.0f;
#pragma unroll 1
        for (int cc = 0; cc < 19; cc++) {
            const int c = 19 * q + cc;
            if (c < NCHUNK) {
                const float v = cend[c * 32 + lane];
                cend[c * 32 + lane] = p;
                p *= v;
            }
        }
        qp[q * 32 + lane] = p;
    }
    __syncthreads();
    if (q > 0) {
        float off = qp[lane];
#pragma unroll
        for (int w = 1; w < 7; w++)
            if (q > w) off *= qp[w * 32 + lane];
#pragma unroll 1
        for (int cc = 0; cc < 19; cc++) {
            const int c = 19 * q + cc;
            if (c < NCHUNK) cend[c * 32 + lane] *= off;
        }
    }
    __syncthreads();

#pragma unroll 1
    for (int ti = 0; ti < 16; ti++) {
        const int t0 = ti * 64;
#pragma unroll
        for (int rr = 0; rr < 8; rr++) {
            const int r = q + 8 * rr;
            const int t = t0 + r;
            if (t == 0) {
                tile[r * 33 + lane] = 1.0f;
            } else {
                const int c = (t - 2) / 7;   // t=1 -> 0
                const float v = g_scratch[(size_t)t * NIJ + ij0 + lane];
                tile[r * 33 + lane] = v * cend[c * 32 + lane];
            }
        }
        __syncthreads();
#pragma unroll
        for (int cc = 0; cc < 8; cc++) {
            const int col = colg + 4 * cc;
            out[(size_t)(ij0 + col) * TT + t0 + lane64] = tile[lane64 * 33 + col];
        }
        __syncthreads();
    }
}

extern "C" void kernel_launch(void* const* d_in, const int* in_sizes, int n_in,
                              void* d_out, int out_size) {
    const float4* X4 = (const float4*)d_in[0];
    const float4* Y4 = (const float4*)d_in[1];
    float* out = (float*)d_out;

    const int smem2 = (NCHUNK * 32 + 8 * 32 + 64 * 33) * (int)sizeof(float);  // 28160 B
    cudaFuncSetAttribute(nsk_phase1, cudaFuncAttributeMaxDynamicSharedMemorySize,
                         SM1_TOTAL);
    cudaFuncSetAttribute(nsk_phase2f, cudaFuncAttributeMaxDynamicSharedMemorySize,
                         smem2);

    // launch pattern [dummy, p1, p2, dummy] puts ncu's "-s 5" sample on p1
    nsk_dummy<<<1, 32>>>();
    nsk_phase1<<<2 * NCHUNK, 256, SM1_TOTAL>>>(X4, Y4);
    nsk_phase2f<<<NIJ / 32, 256, smem2>>>(out);
    nsk_dummy<<<1, 32>>>();
}

// round 16
// speedup vs baseline: 1.2180x; 1.0411x over previous
#include <cuda_runtime.h>
#include <cuda_bf16.h>
#include <cstdint>

#define TT 1024
#define BX 128
#define NIJ (BX * BX)
#define NCHUNK 146       // chunk 0: steps [0,8); chunk c>0: [7c+1, 7c+8)
#define BUFB 69632       // one tile buffer: A (128x272B) + B (128x272B)

// scratch: local prefix products, layout [t][i*128+j]; 64 MB
__device__ float g_scratch[TT * NIJ];

__device__ __forceinline__ uint32_t smem_u32(const void* p) {
    uint32_t a;
    asm("{ .reg .u64 t; cvta.to.shared.u64 t, %1; cvt.u32.u64 %0, t; }"
        : "=r"(a) : "l"(p));
    return a;
}
__device__ __forceinline__ void ldsm_x4(uint32_t& r0, uint32_t& r1,
                                        uint32_t& r2, uint32_t& r3,
                                        uint32_t addr) {
    asm volatile("ldmatrix.sync.aligned.m8n8.x4.shared.b16 {%0,%1,%2,%3}, [%4];"
                 : "=r"(r0), "=r"(r1), "=r"(r2), "=r"(r3) : "r"(addr));
}
__device__ __forceinline__ void mma16816(float* c, const uint32_t* a,
                                         uint32_t b0, uint32_t b1) {
    asm volatile(
        "mma.sync.aligned.m16n8k16.row.col.f32.bf16.bf16.f32 "
        "{%0,%1,%2,%3}, {%4,%5,%6,%7}, {%8,%9}, {%0,%1,%2,%3};"
        : "+f"(c[0]), "+f"(c[1]), "+f"(c[2]), "+f"(c[3])
        : "r"(a[0]), "r"(a[1]), "r"(a[2]), "r"(a[3]), "r"(b0), "r"(b1));
}
__device__ __forceinline__ uint32_t bcat(__nv_bfloat16 a, __nv_bfloat16 b) {
    __nv_bfloat162 t = __halves2bfloat162(a, b);
    return *reinterpret_cast<uint32_t*>(&t);
}

// Convert one step's diffs to bf16 hi/lo tiles (A=[Xhi|Xlo], B=[Yhi|Ylo],
// row stride 272B) in buffer (t & 1). Per-thread: row crow, d-quad cq.
__device__ __forceinline__ void convert_step(char* smc, int t, int crow, int cq,
                                             const float4* __restrict__ X4,
                                             const float4* __restrict__ Y4) {
    char* bufc = smc + (t & 1) * BUFB;
    const int gb = crow * 16384 + t * 16 + cq * 4;
    {
        float fx[16];
#pragma unroll
        for (int c = 0; c < 4; ++c) {
            float4 a0 = X4[gb + c], a1 = X4[gb + 16 + c];
            fx[4 * c + 0] = (a1.x - a0.x) * 1023.0f;
            fx[4 * c + 1] = (a1.y - a0.y) * 1023.0f;
            fx[4 * c + 2] = (a1.z - a0.z) * 1023.0f;
            fx[4 * c + 3] = (a1.w - a0.w) * 1023.0f;
        }
        uint32_t xh[8], xl[8];
#pragma unroll
        for (int m = 0; m < 8; ++m) {
            float u = fx[2 * m], v = fx[2 * m + 1];
            __nv_bfloat16 uh = __float2bfloat16_rn(u);
            __nv_bfloat16 vh = __float2bfloat16_rn(v);
            xh[m] = bcat(uh, vh);
            xl[m] = bcat(__float2bfloat16_rn(u - __bfloat162float(uh)),
                         __float2bfloat16_rn(v - __bfloat162float(vh)));
        }
        char* pa = bufc + crow * 272 + cq * 32;
        ((uint4*)pa)[0] = ((uint4*)xh)[0];
        ((uint4*)(pa + 16))[0] = ((uint4*)xh)[1];
        ((uint4*)(pa + 128))[0] = ((uint4*)xl)[0];
        ((uint4*)(pa + 144))[0] = ((uint4*)xl)[1];
    }
    {
        float fy[16];
#pragma unroll
        for (int c = 0; c < 4; ++c) {
            float4 b0 = Y4[gb + c], b1 = Y4[gb + 16 + c];
            fy[4 * c + 0] = b1.x - b0.x;
            fy[4 * c + 1] = b1.y - b0.y;
            fy[4 * c + 2] = b1.z - b0.z;
            fy[4 * c + 3] = b1.w - b0.w;
        }
        uint32_t yh[8], yl[8];
#pragma unroll
        for (int m = 0; m < 8; ++m) {
            float p = fy[2 * m], q = fy[2 * m + 1];
            __nv_bfloat16 ph = __float2bfloat16_rn(p);
            __nv_bfloat16 qh = __float2bfloat16_rn(q);
            yh[m] = bcat(ph, qh);
            yl[m] = bcat(__float2bfloat16_rn(p - __bfloat162float(ph)),
                         __float2bfloat16_rn(q - __bfloat162float(qh)));
        }
        char* pb = bufc + 34816 + crow * 272 + cq * 32;
        ((uint4*)pb)[0] = ((uint4*)yh)[0];
        ((uint4*)(pb + 16))[0] = ((uint4*)yh)[1];
        ((uint4*)(pb + 128))[0] = ((uint4*)yl)[0];
        ((uint4*)(pb + 144))[0] = ((uint4*)yl)[1];
    }
}

// Phase 1 (HMMA, intra-warp pipelined): block b handles steps [7b+1, 7b+8)
// (block 0: [0,8)). Per step: Z = (1023 dX) dY^T, bf16 split, hh+hl+lh by
// k-chunk pairing. Loop body: bar -> issue ldsm+MMA(s) -> convert+STS(s+1)
// (LDG latency drains under the in-flight HMMAs) -> EPI(s). One barrier per
// step; tiles double-buffered by s&1.
__global__ __launch_bounds__(512, 1)
void nsk_phase1(const float4* __restrict__ X4, const float4* __restrict__ Y4) {
    extern __shared__ char smc[];
    const uint32_t sb = smem_u32(smc);

    const int tid = threadIdx.x;
    const int wid = tid >> 5;
    const int lane = tid & 31;

    // conversion role
    const int crow = tid >> 2;           // 0..127
    const int cq = tid & 3;              // d-quad of 16
    // mma tile role: 16 warps, 4x4
    const int m0 = (wid >> 2) << 5;
    const int n0 = (wid & 3) << 5;
    const int grp = lane >> 3, lrow = lane & 7;
    const uint32_t offA = (uint32_t)((lrow + 8 * (grp & 1)) * 272 + 16 * (grp >> 1));
    const uint32_t offB = (uint32_t)((lrow + 8 * (grp >> 1)) * 272 + 16 * (grp & 1));
    const int g = lane >> 2, tg = lane & 3;

    const int b = blockIdx.x;
    const int s_start = (b == 0) ? 0 : 7 * b + 1;
    const int s_end = 7 * b + 8;         // max 1023 at b=145

    float k[2][4][4];
#pragma unroll
    for (int a = 0; a < 2; a++)
#pragma unroll
        for (int c = 0; c < 4; c++)
#pragma unroll
            for (int e = 0; e < 4; e++) k[a][c][e] = 1.0f;

    // prologue: tiles for the first step
    convert_step(smc, s_start, crow, cq, X4, Y4);

    for (int s = s_start; s < s_end; ++s) {
        __syncthreads();   // STS(s) complete; ldsm reads of buf (s+1)&1 done

        const uint32_t aA = sb + (s & 1) * BUFB;
        const uint32_t aB = aA + 34816;

        // ---- issue MMA(s): 4 k-chunks, hh + hl + lh
        float cacc[2][4][4];
#pragma unroll
        for (int mf = 0; mf < 2; mf++)
#pragma unroll
            for (int nf = 0; nf < 4; nf++)
#pragma unroll
                for (int e = 0; e < 4; e++) cacc[mf][nf][e] = 0.0f;

#pragma unroll
        for (int kc = 0; kc < 4; ++kc) {
            const uint32_t kh = kc * 32;
            const uint32_t kl = 128 + kc * 32;
            uint32_t ah0[4], ah1[4], al0[4], al1[4];
            uint32_t bh0[4], bh1[4], bl0[4], bl1[4];
            ldsm_x4(ah0[0], ah0[1], ah0[2], ah0[3], aA + m0 * 272 + kh + offA);
            ldsm_x4(ah1[0], ah1[1], ah1[2], ah1[3], aA + (m0 + 16) * 272 + kh + offA);
            ldsm_x4(al0[0], al0[1], al0[2], al0[3], aA + m0 * 272 + kl + offA);
            ldsm_x4(al1[0], al1[1], al1[2], al1[3], aA + (m0 + 16) * 272 + kl + offA);
            ldsm_x4(bh0[0], bh0[1], bh0[2], bh0[3], aB + n0 * 272 + kh + offB);
            ldsm_x4(bh1[0], bh1[1], bh1[2], bh1[3], aB + (n0 + 16) * 272 + kh + offB);
            ldsm_x4(bl0[0], bl0[1], bl0[2], bl0[3], aB + n0 * 272 + kl + offB);
            ldsm_x4(bl1[0], bl1[1], bl1[2], bl1[3], aB + (n0 + 16) * 272 + kl + offB);
            mma16816(cacc[0][0], ah0, bh0[0], bh0[1]);
            mma16816(cacc[0][1], ah0, bh0[2], bh0[3]);
            mma16816(cacc[0][2], ah0, bh1[0], bh1[1]);
            mma16816(cacc[0][3], ah0, bh1[2], bh1[3]);
            mma16816(cacc[1][0], ah1, bh0[0], bh0[1]);
            mma16816(cacc[1][1], ah1, bh0[2], bh0[3]);
            mma16816(cacc[1][2], ah1, bh1[0], bh1[1]);
            mma16816(cacc[1][3], ah1, bh1[2], bh1[3]);
            mma16816(cacc[0][0], ah0, bl0[0], bl0[1]);
            mma16816(cacc[0][1], ah0, bl0[2], bl0[3]);
            mma16816(cacc[0][2], ah0, bl1[0], bl1[1]);
            mma16816(cacc[0][3], ah0, bl1[2], bl1[3]);
            mma16816(cacc[1][0], ah1, bl0[0], bl0[1]);
            mma16816(cacc[1][1], ah1, bl0[2], bl0[3]);
            mma16816(cacc[1][2], ah1, bl1[0], bl1[1]);
            mma16816(cacc[1][3], ah1, bl1[2], bl1[3]);
            mma16816(cacc[0][0], al0, bh0[0], bh0[1]);
            mma16816(cacc[0][1], al0, bh0[2], bh0[3]);
            mma16816(cacc[0][2], al0, bh1[0], bh1[1]);
            mma16816(cacc[0][3], al0, bh1[2], bh1[3]);
            mma16816(cacc[1][0], al1, bh0[0], bh0[1]);
            mma16816(cacc[1][1], al1, bh0[2], bh0[3]);
            mma16816(cacc[1][2], al1, bh1[0], bh1[1]);
            mma16816(cacc[1][3], al1, bh1[2], bh1[3]);
        }

        // ---- convert+STS for step s+1 (overlaps HMMA drain; buffer (s+1)&1
        // is safe: its last ldsm readers ran in step s-1, before this bar)
        if (s + 1 < s_end)
            convert_step(smc, s + 1, crow, cq, X4, Y4);

        // ---- epilogue: waits on HMMA results; k *= (1+z); float2 stores
        float* base = g_scratch + (size_t)(s + 1) * NIJ;
#pragma unroll
        for (int mf = 0; mf < 2; mf++) {
#pragma unroll
            for (int nf = 0; nf < 4; nf++) {
                const int i0 = m0 + mf * 16 + g;
                const int j = n0 + nf * 8 + tg * 2;
                float* c4 = cacc[mf][nf];
                float* kk = k[mf][nf];
                float k0 = fmaf(c4[0], kk[0], kk[0]);
                float k1 = fmaf(c4[1], kk[1], kk[1]);
                float k2 = fmaf(c4[2], kk[2], kk[2]);
                float k3 = fmaf(c4[3], kk[3], kk[3]);
                kk[0] = k0; kk[1] = k1; kk[2] = k2; kk[3] = k3;
                *(float2*)(base + i0 * BX + j) = make_float2(k0, k1);
                *(float2*)(base + (i0 + 8) * BX + j) = make_float2(k2, k3);
            }
        }
    }
}

// Phase 2 (fused, verified R12 version): one block per 32-ij strip.
// Chunk c's last written t is e = 7c+8; owner of t>=1 is c = (t-2)/7.
__global__ __launch_bounds__(256, 8)
void nsk_phase2f(float* __restrict__ out) {
    extern __shared__ float sm[];
    float* cend = sm;                    // [146][32] -> exclusive scales
    float* qp = sm + NCHUNK * 32;        // [8][32]
    float* tile = qp + 8 * 32;           // [64][33]

    const int tid = threadIdx.x;
    const int lane = tid & 31;
    const int q = tid >> 5;              // 0..7
    const int lane64 = tid & 63;
    const int colg = tid >> 6;           // 0..3
    const int ij0 = blockIdx.x * 32;

#pragma unroll
    for (int cc = 0; cc < 19; cc++) {
        const int c = q + 8 * cc;
        if (c < NCHUNK) {
            const int e = 7 * c + 8;
            cend[c * 32 + lane] = g_scratch[(size_t)e * NIJ + ij0 + lane];
        }
    }
    __syncthreads();
    {
        float p = 1.0f;
#pragma unroll 1
        for (int cc = 0; cc < 19; cc++) {
            const int c = 19 * q + cc;
            if (c < NCHUNK) {
                const float v = cend[c * 32 + lane];
                cend[c * 32 + lane] = p;
                p *= v;
            }
        }
        qp[q * 32 + lane] = p;
    }
    __syncthreads();
    if (q > 0) {
        float off = qp[lane];
#pragma unroll
        for (int w = 1; w < 7; w++)
            if (q > w) off *= qp[w * 32 + lane];
#pragma unroll 1
        for (int cc = 0; cc < 19; cc++) {
            const int c = 19 * q + cc;
            if (c < NCHUNK) cend[c * 32 + lane] *= off;
        }
    }
    __syncthreads();

#pragma unroll 1
    for (int ti = 0; ti < 16; ti++) {
        const int t0 = ti * 64;
#pragma unroll
        for (int rr = 0; rr < 8; rr++) {
            const int r = q + 8 * rr;
            const int t = t0 + r;
            if (t == 0) {
                tile[r * 33 + lane] = 1.0f;
            } else {
                const int c = (t - 2) / 7;   // t=1 -> 0
                const float v = g_scratch[(size_t)t * NIJ + ij0 + lane];
                tile[r * 33 + lane] = v * cend[c * 32 + lane];
            }
        }
        __syncthreads();
#pragma unroll
        for (int cc = 0; cc < 8; cc++) {
            const int col = colg + 4 * cc;
            out[(size_t)(ij0 + col) * TT + t0 + lane64] = tile[lane64 * 33 + col];
        }
        __syncthreads();
    }
}

extern "C" void kernel_launch(void* const* d_in, const int* in_sizes, int n_in,
                              void* d_out, int out_size) {
    const float4* X4 = (const float4*)d_in[0];
    const float4* Y4 = (const float4*)d_in[1];
    float* out = (float*)d_out;

    const int smem1 = 2 * BUFB;                                               // 139264 B
    const int smem2 = (NCHUNK * 32 + 8 * 32 + 64 * 33) * (int)sizeof(float);  // 28160 B
    cudaFuncSetAttribute(nsk_phase1, cudaFuncAttributeMaxDynamicSharedMemorySize, smem1);
    cudaFuncSetAttribute(nsk_phase2f, cudaFuncAttributeMaxDynamicSharedMemorySize, smem2);

    nsk_phase1<<<NCHUNK, 512, smem1>>>(X4, Y4);
    nsk_phase2f<<<NIJ / 32, 256, smem2>>>(out);
}